// round 1
// baseline (speedup 1.0000x reference)
#include <cuda_runtime.h>

#define Bn    2
#define CHn   256
#define Hn    512
#define Wn    512
#define HW    (Hn*Wn)          // 262144 = 2^18
#define NPIX  (Bn*HW)          // 524288
#define NITER 5

// -------- persistent scratch (no allocations allowed) --------
__device__ uchar4        g_img[NPIX];          // r,g,b quantized + flags (bit0 fixed, bit1 fixed_fg)
__device__ unsigned char g_alpha[2][NPIX];     // ping-pong alpha
__device__ unsigned int  g_minmax[Bn][2];      // flipped-float bits: [min, max]
__device__ int           g_acc[NITER][Bn][4];  // fg stats per iteration slot: r,g,b,count
__device__ int           g_tot[Bn][4];         // total r,g,b (count == HW)

// -------- ordered-uint float min/max trick --------
__device__ __forceinline__ unsigned int fflip(float f) {
    unsigned u = __float_as_uint(f);
    return (u & 0x80000000u) ? ~u : (u | 0x80000000u);
}
__device__ __forceinline__ float funflip(unsigned u) {
    return (u & 0x80000000u) ? __uint_as_float(u & 0x7FFFFFFFu) : __uint_as_float(~u);
}

// ============================================================
__global__ void k_init() {
    int t = threadIdx.x;
    if (t < Bn) { g_minmax[t][0] = 0xFFFFFFFFu; g_minmax[t][1] = 0u; }
    if (t < NITER * Bn * 4) ((int*)g_acc)[t] = 0;
    if (t < Bn * 4)         ((int*)g_tot)[t] = 0;
}

// per-batch min/max over channels 0..2
__global__ void k_minmax(const float* __restrict__ feat) {
    int b = blockIdx.y;
    const float4* p = (const float4*)(feat + (size_t)b * CHn * HW);
    const int n4 = 3 * HW / 4;
    unsigned lmin = 0xFFFFFFFFu, lmax = 0u;
    for (int i = blockIdx.x * blockDim.x + threadIdx.x; i < n4;
         i += gridDim.x * blockDim.x) {
        float4 v = p[i];
        unsigned a = fflip(v.x), c = fflip(v.y), d = fflip(v.z), e = fflip(v.w);
        unsigned m0 = min(min(a, c), min(d, e));
        unsigned m1 = max(max(a, c), max(d, e));
        lmin = min(lmin, m0);
        lmax = max(lmax, m1);
    }
    lmin = __reduce_min_sync(0xFFFFFFFFu, lmin);
    lmax = __reduce_max_sync(0xFFFFFFFFu, lmax);
    __shared__ unsigned smin[8], smax[8];
    int w = threadIdx.x >> 5;
    if ((threadIdx.x & 31) == 0) { smin[w] = lmin; smax[w] = lmax; }
    __syncthreads();
    if (threadIdx.x == 0) {
        int nw = blockDim.x >> 5;
        unsigned m0 = smin[0], m1 = smax[0];
        for (int i = 1; i < nw; i++) { m0 = min(m0, smin[i]); m1 = max(m1, smax[i]); }
        atomicMin(&g_minmax[b][0], m0);
        atomicMax(&g_minmax[b][1], m1);
    }
}

// quantize img, build trimap flags, write alpha0, accumulate slot-0 + totals
__global__ void k_setup(const float* __restrict__ feat, const int* __restrict__ mask) {
    int idx = blockIdx.x * blockDim.x + threadIdx.x;   // < NPIX
    int b   = idx >> 18;
    int pix = idx & (HW - 1);
    int y = pix >> 9, x = pix & (Wn - 1);

    float mn = funflip(g_minmax[b][0]);
    float mx = funflip(g_minmax[b][1]);
    float denom = __fadd_rn(__fsub_rn(mx, mn), 1e-12f);

    const float* base = feat + (size_t)b * CHn * HW + pix;
    int q[3];
#pragma unroll
    for (int c = 0; c < 3; c++) {
        float v = base[c * HW];
        float t = __fmul_rn(__fdiv_rn(__fsub_rn(v, mn), denom), 255.0f);
        t = fminf(fmaxf(floorf(t), 0.0f), 255.0f);
        q[c] = (int)t;
    }

    int m = mask[idx];
    bool center = (y >= 230) && (y < 281) && (x >= 230) && (x < 281);
    bool border = (y < 51) || (y >= 461) || (x < 51) || (x >= 461);
    int tri = center ? 1 : (border ? 0 : (m == 1 ? 3 : 2));
    unsigned char flags = (unsigned char)(((tri <= 1) ? 1 : 0) | ((tri == 1) ? 2 : 0));
    int a0 = (tri == 1 || tri == 3) ? 1 : 0;

    g_img[idx]      = make_uchar4((unsigned char)q[0], (unsigned char)q[1],
                                  (unsigned char)q[2], flags);
    g_alpha[0][idx] = (unsigned char)a0;

    // block-reduce 7 integer sums, then one atomic set per block
    __shared__ int ssum[8];
    if (threadIdx.x < 8) ssum[threadIdx.x] = 0;
    __syncthreads();
    int w0 = __reduce_add_sync(0xFFFFFFFFu, a0 ? q[0] : 0);
    int w1 = __reduce_add_sync(0xFFFFFFFFu, a0 ? q[1] : 0);
    int w2 = __reduce_add_sync(0xFFFFFFFFu, a0 ? q[2] : 0);
    int w3 = __reduce_add_sync(0xFFFFFFFFu, a0);
    int w4 = __reduce_add_sync(0xFFFFFFFFu, q[0]);
    int w5 = __reduce_add_sync(0xFFFFFFFFu, q[1]);
    int w6 = __reduce_add_sync(0xFFFFFFFFu, q[2]);
    if ((threadIdx.x & 31) == 0) {
        atomicAdd(ssum + 0, w0); atomicAdd(ssum + 1, w1);
        atomicAdd(ssum + 2, w2); atomicAdd(ssum + 3, w3);
        atomicAdd(ssum + 4, w4); atomicAdd(ssum + 5, w5);
        atomicAdd(ssum + 6, w6);
    }
    __syncthreads();
    if (threadIdx.x < 4)      atomicAdd(&g_acc[0][b][threadIdx.x], ssum[threadIdx.x]);
    else if (threadIdx.x < 7) atomicAdd(&g_tot[b][threadIdx.x - 4], ssum[threadIdx.x]);
}

// one ICM relabel iteration; also accumulates next iteration's fg stats
__global__ void k_iter(int it, float* __restrict__ out, int last) {
    const unsigned char* __restrict__ ain = g_alpha[it & 1];
    unsigned char* aout = g_alpha[(it + 1) & 1];

    int idx = blockIdx.x * blockDim.x + threadIdx.x;
    int b   = idx >> 18;
    int pix = idx & (HW - 1);
    int y = pix >> 9, x = pix & (Wn - 1);

    __shared__ float fm[3], bm[3];
    __shared__ int ssum[4];
    if (threadIdx.x == 0) {
        int F0 = g_acc[it][b][0], F1 = g_acc[it][b][1];
        int F2 = g_acc[it][b][2], Fc = g_acc[it][b][3];
        int T0 = g_tot[b][0], T1 = g_tot[b][1], T2 = g_tot[b][2];
        float fc = __fadd_rn((float)Fc, 1e-6f);
        float bc = __fadd_rn((float)(HW - Fc), 1e-6f);
        fm[0] = __fdiv_rn((float)F0, fc);
        fm[1] = __fdiv_rn((float)F1, fc);
        fm[2] = __fdiv_rn((float)F2, fc);
        bm[0] = __fdiv_rn((float)(T0 - F0), bc);
        bm[1] = __fdiv_rn((float)(T1 - F1), bc);
        bm[2] = __fdiv_rn((float)(T2 - F2), bc);
    }
    if (threadIdx.x < 4) ssum[threadIdx.x] = 0;
    __syncthreads();

    uchar4 im = g_img[idx];
    float i0 = (float)im.x, i1 = (float)im.y, i2 = (float)im.z;

    int up = ain[(y > 0)      ? idx - Wn : idx];
    int dn = ain[(y < Hn - 1) ? idx + Wn : idx];
    int lf = ain[(x > 0)      ? idx - 1  : idx];
    int rt = ain[(x < Wn - 1) ? idx + 1  : idx];
    float nb = __fmul_rn((float)(up + dn + lf + rt), 0.25f);

    float d0 = __fsub_rn(i0, fm[0]);
    float d1 = __fsub_rn(i1, fm[1]);
    float d2 = __fsub_rn(i2, fm[2]);
    float dfg = __fadd_rn(__fadd_rn(__fmul_rn(d0, d0), __fmul_rn(d1, d1)),
                          __fmul_rn(d2, d2));
    float e0 = __fsub_rn(i0, bm[0]);
    float e1 = __fsub_rn(i1, bm[1]);
    float e2 = __fsub_rn(i2, bm[2]);
    float dbg = __fadd_rn(__fadd_rn(__fmul_rn(e0, e0), __fmul_rn(e1, e1)),
                          __fmul_rn(e2, e2));
    float pw    = __fmul_rn(50.0f, __fsub_rn(__fmul_rn(2.0f, nb), 1.0f));
    float score = __fadd_rn(__fsub_rn(dbg, dfg), pw);

    int na    = (score > 0.0f) ? 1 : 0;
    int fixed = im.w & 1;
    int ffg   = (im.w >> 1) & 1;
    int a     = fixed ? ffg : na;

    if (last) {
        out[idx] = (float)a;
    } else {
        aout[idx] = (unsigned char)a;
        int w0 = __reduce_add_sync(0xFFFFFFFFu, a ? (int)im.x : 0);
        int w1 = __reduce_add_sync(0xFFFFFFFFu, a ? (int)im.y : 0);
        int w2 = __reduce_add_sync(0xFFFFFFFFu, a ? (int)im.z : 0);
        int w3 = __reduce_add_sync(0xFFFFFFFFu, a);
        if ((threadIdx.x & 31) == 0) {
            atomicAdd(ssum + 0, w0); atomicAdd(ssum + 1, w1);
            atomicAdd(ssum + 2, w2); atomicAdd(ssum + 3, w3);
        }
        __syncthreads();
        if (threadIdx.x < 4)
            atomicAdd(&g_acc[it + 1][b][threadIdx.x], ssum[threadIdx.x]);
    }
}

// ============================================================
extern "C" void kernel_launch(void* const* d_in, const int* in_sizes, int n_in,
                              void* d_out, int out_size) {
    const float* feat = (const float*)d_in[0];
    const int*   mask = (const int*)d_in[1];
    float*       out  = (float*)d_out;

    k_init<<<1, 64>>>();
    k_minmax<<<dim3(128, Bn), 256>>>(feat);
    k_setup<<<NPIX / 256, 256>>>(feat, mask);
    for (int it = 0; it < NITER; ++it)
        k_iter<<<NPIX / 256, 256>>>(it, out, (it == NITER - 1) ? 1 : 0);
}

// round 2
// speedup vs baseline: 1.0490x; 1.0490x over previous
#include <cuda_runtime.h>

#define Bn    2
#define CHn   256
#define Hn    512
#define Wn    512
#define HW    (Hn*Wn)           // 262144
#define NPIX  (Bn*HW)           // 524288
#define NITER 5
#define NB    512               // blocks (all resident in wave 1)
#define NT    256               // threads/block
#define NTHREADS (NB*NT)        // 131072 -> 4 px/thread

// -------- persistent scratch --------
__device__ uchar4        g_img[NPIX];          // r,g,b + flags(bit0 fixed, bit1 fixed_fg)
__device__ unsigned char g_alpha[2][NPIX];     // ping-pong alpha
__device__ unsigned int  g_minmax[Bn][2];      // flipped-float bits [min,max]
__device__ int           g_acc[NITER][Bn][4];  // fg stats per iter: r,g,b,count
__device__ int           g_tot[Bn][4];         // total r,g,b
__device__ unsigned int  g_barcnt;             // grid-barrier monotonic counter

__device__ __forceinline__ unsigned int fflip(float f) {
    unsigned u = __float_as_uint(f);
    return (u & 0x80000000u) ? ~u : (u | 0x80000000u);
}
__device__ __forceinline__ float funflip(unsigned u) {
    return (u & 0x80000000u) ? __uint_as_float(u & 0x7FFFFFFFu) : __uint_as_float(~u);
}

// monotonic-counter grid barrier (all NB blocks resident by construction)
__device__ __forceinline__ void gbar(int& phase) {
    phase++;
    __syncthreads();
    if (threadIdx.x == 0) {
        __threadfence();
        atomicAdd(&g_barcnt, 1u);
        const volatile unsigned* p = &g_barcnt;
        const unsigned tgt = (unsigned)phase * NB;
        while (*p < tgt) { }
        __threadfence();
    }
    __syncthreads();
}

__device__ __forceinline__ int qz(float v, float mn, float denom) {
    float t = __fmul_rn(__fdiv_rn(__fsub_rn(v, mn), denom), 255.0f);
    t = fminf(fmaxf(floorf(t), 0.0f), 255.0f);
    return (int)t;
}

// ============================================================
__global__ void k_init() {
    int t = threadIdx.x;
    if (t < Bn) { g_minmax[t][0] = 0xFFFFFFFFu; g_minmax[t][1] = 0u; }
    if (t < NITER * Bn * 4) ((int*)g_acc)[t] = 0;
    if (t < Bn * 4)         ((int*)g_tot)[t] = 0;
    if (t == 0) g_barcnt = 0u;
}

// ============================================================
__global__ void __launch_bounds__(NT, 4)
k_main(const float* __restrict__ feat, const int* __restrict__ mask,
       float* __restrict__ out) {
    const int tid  = threadIdx.x;
    const int gtid = blockIdx.x * NT + tid;
    int phase = 0;

    __shared__ unsigned sredA[NT / 32], sredB[NT / 32];
    __shared__ float sm_fm[3], sm_bm[3];
    __shared__ int   ssum[8];

    // ---------- phase 1: per-batch min/max over channels 0..2 ----------
    for (int b = 0; b < Bn; b++) {
        const float4* p = (const float4*)(feat + (size_t)b * CHn * HW);
        unsigned lmin = 0xFFFFFFFFu, lmax = 0u;
        for (int i = gtid; i < 3 * HW / 4; i += NTHREADS) {
            float4 v = p[i];
            unsigned a = fflip(v.x), c = fflip(v.y), d = fflip(v.z), e = fflip(v.w);
            lmin = min(lmin, min(min(a, c), min(d, e)));
            lmax = max(lmax, max(max(a, c), max(d, e)));
        }
        lmin = __reduce_min_sync(0xFFFFFFFFu, lmin);
        lmax = __reduce_max_sync(0xFFFFFFFFu, lmax);
        if ((tid & 31) == 0) { sredA[tid >> 5] = lmin; sredB[tid >> 5] = lmax; }
        __syncthreads();
        if (tid == 0) {
            unsigned m0 = sredA[0], m1 = sredB[0];
            for (int i = 1; i < NT / 32; i++) { m0 = min(m0, sredA[i]); m1 = max(m1, sredB[i]); }
            atomicMin(&g_minmax[b][0], m0);
            atomicMax(&g_minmax[b][1], m1);
        }
        __syncthreads();
    }
    gbar(phase);

    // ---------- phase 2: quantize + trimap + alpha0 + stats ----------
    const int idx4 = gtid;               // word index (4 px each)
    const int bb   = idx4 >> 16;         // batch (constant per block)
    const int pix  = (idx4 & 0xFFFF) << 2;
    const int y = pix >> 9, x = pix & (Wn - 1);   // x multiple of 4

    {
        float mn = funflip(__ldcg((const unsigned*)&g_minmax[bb][0]));
        float mx = funflip(__ldcg((const unsigned*)&g_minmax[bb][1]));
        float denom = __fadd_rn(__fsub_rn(mx, mn), 1e-12f);

        const float* base = feat + (size_t)bb * CHn * HW + pix;
        float4 c0 = *(const float4*)(base);
        float4 c1 = *(const float4*)(base + HW);
        float4 c2 = *(const float4*)(base + 2 * HW);
        int4   mk = ((const int4*)mask)[idx4];

        float r[4]  = {c0.x, c0.y, c0.z, c0.w};
        float g[4]  = {c1.x, c1.y, c1.z, c1.w};
        float bl[4] = {c2.x, c2.y, c2.z, c2.w};
        int   mm[4] = {mk.x, mk.y, mk.z, mk.w};

        unsigned imw[4], aw = 0;
        int sfr = 0, sfg = 0, sfb = 0, sfc = 0, str = 0, stg = 0, stb = 0;
        const bool yc = (y >= 230) && (y < 281);
        const bool yb = (y < 51) || (y >= 461);
#pragma unroll
        for (int j = 0; j < 4; j++) {
            int q0 = qz(r[j], mn, denom);
            int q1 = qz(g[j], mn, denom);
            int q2 = qz(bl[j], mn, denom);
            int xj = x + j;
            bool center = yc && (xj >= 230) && (xj < 281);
            bool border = yb || (xj < 51) || (xj >= 461);
            int tri = center ? 1 : (border ? 0 : (mm[j] == 1 ? 3 : 2));
            int flags = ((tri <= 1) ? 1 : 0) | ((tri == 1) ? 2 : 0);
            int a0 = (tri == 1 || tri == 3) ? 1 : 0;
            imw[j] = (unsigned)q0 | ((unsigned)q1 << 8) | ((unsigned)q2 << 16)
                   | ((unsigned)flags << 24);
            aw |= (unsigned)a0 << (8 * j);
            if (a0) { sfr += q0; sfg += q1; sfb += q2; sfc++; }
            str += q0; stg += q1; stb += q2;
        }
        ((uint4*)g_img)[idx4] = make_uint4(imw[0], imw[1], imw[2], imw[3]);
        ((unsigned*)g_alpha[0])[idx4] = aw;

        if (tid < 8) ssum[tid] = 0;
        __syncthreads();
        int w0 = __reduce_add_sync(0xFFFFFFFFu, sfr);
        int w1 = __reduce_add_sync(0xFFFFFFFFu, sfg);
        int w2 = __reduce_add_sync(0xFFFFFFFFu, sfb);
        int w3 = __reduce_add_sync(0xFFFFFFFFu, sfc);
        int w4 = __reduce_add_sync(0xFFFFFFFFu, str);
        int w5 = __reduce_add_sync(0xFFFFFFFFu, stg);
        int w6 = __reduce_add_sync(0xFFFFFFFFu, stb);
        if ((tid & 31) == 0) {
            atomicAdd(ssum + 0, w0); atomicAdd(ssum + 1, w1);
            atomicAdd(ssum + 2, w2); atomicAdd(ssum + 3, w3);
            atomicAdd(ssum + 4, w4); atomicAdd(ssum + 5, w5);
            atomicAdd(ssum + 6, w6);
        }
        __syncthreads();
        if (tid < 4)      atomicAdd(&g_acc[0][bb][tid], ssum[tid]);
        else if (tid < 7) atomicAdd(&g_tot[bb][tid - 4], ssum[tid]);
    }
    gbar(phase);

    // ---------- phase 3: 5 ICM iterations ----------
    const uint4 iw = ((const uint4*)g_img)[idx4];   // L1-resident after first use
    const unsigned wv[4] = {iw.x, iw.y, iw.z, iw.w};

    for (int it = 0; it < NITER; ++it) {
        if (tid == 0) {
            int F0 = __ldcg(&g_acc[it][bb][0]);
            int F1 = __ldcg(&g_acc[it][bb][1]);
            int F2 = __ldcg(&g_acc[it][bb][2]);
            int Fc = __ldcg(&g_acc[it][bb][3]);
            int T0 = __ldcg(&g_tot[bb][0]);
            int T1 = __ldcg(&g_tot[bb][1]);
            int T2 = __ldcg(&g_tot[bb][2]);
            float fc = __fadd_rn((float)Fc, 1e-6f);
            float bc = __fadd_rn((float)(HW - Fc), 1e-6f);
            sm_fm[0] = __fdiv_rn((float)F0, fc);
            sm_fm[1] = __fdiv_rn((float)F1, fc);
            sm_fm[2] = __fdiv_rn((float)F2, fc);
            sm_bm[0] = __fdiv_rn((float)(T0 - F0), bc);
            sm_bm[1] = __fdiv_rn((float)(T1 - F1), bc);
            sm_bm[2] = __fdiv_rn((float)(T2 - F2), bc);
        }
        if (tid < 4) ssum[tid] = 0;
        __syncthreads();

        const unsigned char* __restrict__ ain = g_alpha[it & 1];
        unsigned cen = ((const unsigned*)ain)[idx4];
        unsigned upw = (y > 0)      ? ((const unsigned*)ain)[idx4 - Wn / 4] : cen;
        unsigned dnw = (y < Hn - 1) ? ((const unsigned*)ain)[idx4 + Wn / 4] : cen;
        unsigned lfb = (x > 0)   ? (unsigned)ain[(idx4 << 2) - 1] : (cen & 255u);
        unsigned rtb = (x < 508) ? (unsigned)ain[(idx4 << 2) + 4] : (cen >> 24);
        unsigned lfw = (cen << 8) | lfb;
        unsigned rtw = (cen >> 8) | (rtb << 24);
        unsigned nbw = __vadd4(__vadd4(upw, dnw), __vadd4(lfw, rtw));

        float fm0 = sm_fm[0], fm1 = sm_fm[1], fm2 = sm_fm[2];
        float bm0 = sm_bm[0], bm1 = sm_bm[1], bm2 = sm_bm[2];

        int av[4];
        int s0 = 0, s1 = 0, s2 = 0, sc = 0;
#pragma unroll
        for (int j = 0; j < 4; j++) {
            unsigned w = wv[j];
            int qi0 = (int)(w & 255u), qi1 = (int)((w >> 8) & 255u),
                qi2 = (int)((w >> 16) & 255u);
            float i0 = (float)qi0, i1 = (float)qi1, i2 = (float)qi2;
            float nb = __fmul_rn((float)((nbw >> (8 * j)) & 255u), 0.25f);

            float d0 = __fsub_rn(i0, fm0);
            float d1 = __fsub_rn(i1, fm1);
            float d2 = __fsub_rn(i2, fm2);
            float dfg = __fadd_rn(__fadd_rn(__fmul_rn(d0, d0), __fmul_rn(d1, d1)),
                                  __fmul_rn(d2, d2));
            float e0 = __fsub_rn(i0, bm0);
            float e1 = __fsub_rn(i1, bm1);
            float e2 = __fsub_rn(i2, bm2);
            float dbg = __fadd_rn(__fadd_rn(__fmul_rn(e0, e0), __fmul_rn(e1, e1)),
                                  __fmul_rn(e2, e2));
            float pw = __fmul_rn(50.0f, __fsub_rn(__fmul_rn(2.0f, nb), 1.0f));
            float score = __fadd_rn(__fsub_rn(dbg, dfg), pw);

            int na = (score > 0.0f) ? 1 : 0;
            int a  = (w & 0x01000000u) ? (int)((w >> 25) & 1u) : na;
            av[j] = a;
            if (a) { s0 += qi0; s1 += qi1; s2 += qi2; sc++; }
        }

        if (it == NITER - 1) {
            ((float4*)out)[idx4] = make_float4((float)av[0], (float)av[1],
                                               (float)av[2], (float)av[3]);
        } else {
            unsigned aw = (unsigned)av[0] | ((unsigned)av[1] << 8)
                        | ((unsigned)av[2] << 16) | ((unsigned)av[3] << 24);
            ((unsigned*)g_alpha[(it + 1) & 1])[idx4] = aw;

            int w0 = __reduce_add_sync(0xFFFFFFFFu, s0);
            int w1 = __reduce_add_sync(0xFFFFFFFFu, s1);
            int w2 = __reduce_add_sync(0xFFFFFFFFu, s2);
            int w3 = __reduce_add_sync(0xFFFFFFFFu, sc);
            if ((tid & 31) == 0) {
                atomicAdd(ssum + 0, w0); atomicAdd(ssum + 1, w1);
                atomicAdd(ssum + 2, w2); atomicAdd(ssum + 3, w3);
            }
            __syncthreads();
            if (tid < 4)
                atomicAdd(&g_acc[it + 1][bb][tid], ssum[tid]);
            gbar(phase);
        }
    }
}

// ============================================================
extern "C" void kernel_launch(void* const* d_in, const int* in_sizes, int n_in,
                              void* d_out, int out_size) {
    const float* feat = (const float*)d_in[0];
    const int*   mask = (const int*)d_in[1];
    float*       out  = (float*)d_out;

    k_init<<<1, 64>>>();
    k_main<<<NB, NT>>>(feat, mask, out);
}

// round 3
// speedup vs baseline: 1.1990x; 1.1430x over previous
#include <cuda_runtime.h>

#define Bn    2
#define CHn   256
#define Hn    512
#define Wn    512
#define HW    (Hn*Wn)            // 262144
#define NPIX  (Bn*HW)            // 524288
#define NITER 5
#define NB    128                // blocks: 1 per SM, 64 per batch
#define NT    1024               // threads/block -> 1 word (4px) per thread
#define NTHREADS (NB*NT)         // 131072 == NPIX/4

// -------- persistent scratch --------
__device__ unsigned char g_alpha[2][NPIX];     // ping-pong; only block-boundary rows used
__device__ unsigned int  g_minmax[Bn][2];      // flipped-float bits [min,max]
__device__ int           g_acc[NITER][Bn][4];  // fg stats per iter: r,g,b,count
__device__ int           g_tot[Bn][4];         // total r,g,b
__device__ unsigned int  g_barcnt;

__device__ __forceinline__ unsigned int fflip(float f) {
    unsigned u = __float_as_uint(f);
    return (u & 0x80000000u) ? ~u : (u | 0x80000000u);
}
__device__ __forceinline__ float funflip(unsigned u) {
    return (u & 0x80000000u) ? __uint_as_float(u & 0x7FFFFFFFu) : __uint_as_float(~u);
}

// grid barrier: threadfence (publish) + monotonic counter + spin
__device__ __forceinline__ void gbar(int& phase) {
    phase++;
    __threadfence();
    __syncthreads();
    if (threadIdx.x == 0) {
        atomicAdd(&g_barcnt, 1u);
        const volatile unsigned* p = &g_barcnt;
        const unsigned tgt = (unsigned)phase * NB;
        while (*p < tgt) { }
    }
    __syncthreads();
    __threadfence();   // acquire side
}

__device__ __forceinline__ int qz(float v, float mn, float denom) {
    float t = __fmul_rn(__fdiv_rn(__fsub_rn(v, mn), denom), 255.0f);
    t = fminf(fmaxf(floorf(t), 0.0f), 255.0f);
    return (int)t;
}

// ============================================================
__global__ void k_init() {
    int t = threadIdx.x;
    if (t < Bn) { g_minmax[t][0] = 0xFFFFFFFFu; g_minmax[t][1] = 0u; }
    if (t < NITER * Bn * 4) ((int*)g_acc)[t] = 0;
    if (t < Bn * 4)         ((int*)g_tot)[t] = 0;
    if (t == 0) g_barcnt = 0u;
}

// ============================================================
__global__ void __launch_bounds__(NT, 1)
k_main(const float* __restrict__ feat, const int* __restrict__ mask,
       float* __restrict__ out) {
    const int tid  = threadIdx.x;
    const int wid  = tid >> 5, lane = tid & 31;
    const int idx4 = blockIdx.x * NT + tid;        // word index (4 px)
    const int bb   = blockIdx.x >> 6;              // batch
    const int pix  = (idx4 & 0xFFFF) << 2;
    const int y    = pix >> 9;                     // row
    const int x    = pix & (Wn - 1);               // col (mult of 4)
    const int lr   = tid >> 7;                     // local row 0..7
    const int c    = tid & 127;                    // word-in-row
    int phase = 0;

    __shared__ unsigned salpha[NT];                // alpha words of this block
    __shared__ int      sred[32][8];
    __shared__ unsigned sredA[32], sredB[32];
    __shared__ float    sm_fm[3], sm_bm[3];

    // ---------- phase 1: per-batch min/max over channels 0..2 ----------
    for (int b = 0; b < Bn; b++) {
        const float4* p = (const float4*)(feat + (size_t)b * CHn * HW);
        unsigned lmin = 0xFFFFFFFFu, lmax = 0u;
        for (int i = idx4; i < 3 * HW / 4; i += NTHREADS) {
            float4 v = p[i];
            unsigned a0 = fflip(v.x), a1 = fflip(v.y), a2 = fflip(v.z), a3 = fflip(v.w);
            lmin = min(lmin, min(min(a0, a1), min(a2, a3)));
            lmax = max(lmax, max(max(a0, a1), max(a2, a3)));
        }
        lmin = __reduce_min_sync(0xFFFFFFFFu, lmin);
        lmax = __reduce_max_sync(0xFFFFFFFFu, lmax);
        if (lane == 0) { sredA[wid] = lmin; sredB[wid] = lmax; }
        __syncthreads();
        if (wid == 0) {
            unsigned m0 = __reduce_min_sync(0xFFFFFFFFu, sredA[lane]);
            unsigned m1 = __reduce_max_sync(0xFFFFFFFFu, sredB[lane]);
            if (lane == 0) { atomicMin(&g_minmax[b][0], m0); atomicMax(&g_minmax[b][1], m1); }
        }
        __syncthreads();
    }
    gbar(phase);

    // ---------- phase 2: quantize + trimap + alpha0 + stats ----------
    unsigned wv[4];      // per-pixel: q0|q1<<8|q2<<16|flags<<24  (registers, whole kernel)
    unsigned aw;         // packed alpha (4 bytes)
    {
        float mn = funflip(__ldcg((const unsigned*)&g_minmax[bb][0]));
        float mx = funflip(__ldcg((const unsigned*)&g_minmax[bb][1]));
        float denom = __fadd_rn(__fsub_rn(mx, mn), 1e-12f);

        const float* base = feat + (size_t)bb * CHn * HW + pix;
        float4 c0 = *(const float4*)(base);
        float4 c1 = *(const float4*)(base + HW);
        float4 c2 = *(const float4*)(base + 2 * HW);
        int4   mk = ((const int4*)mask)[idx4];

        float rr[4] = {c0.x, c0.y, c0.z, c0.w};
        float gg[4] = {c1.x, c1.y, c1.z, c1.w};
        float bl[4] = {c2.x, c2.y, c2.z, c2.w};
        int   mm[4] = {mk.x, mk.y, mk.z, mk.w};

        aw = 0;
        int s[7] = {0, 0, 0, 0, 0, 0, 0};
        const bool yc = (y >= 230) && (y < 281);
        const bool yb = (y < 51) || (y >= 461);
#pragma unroll
        for (int j = 0; j < 4; j++) {
            int q0 = qz(rr[j], mn, denom);
            int q1 = qz(gg[j], mn, denom);
            int q2 = qz(bl[j], mn, denom);
            int xj = x + j;
            bool center = yc && (xj >= 230) && (xj < 281);
            bool border = yb || (xj < 51) || (xj >= 461);
            int tri = center ? 1 : (border ? 0 : (mm[j] == 1 ? 3 : 2));
            int flags = ((tri <= 1) ? 1 : 0) | ((tri == 1) ? 2 : 0);
            int a0 = (tri == 1 || tri == 3) ? 1 : 0;
            wv[j] = (unsigned)q0 | ((unsigned)q1 << 8) | ((unsigned)q2 << 16)
                  | ((unsigned)flags << 24);
            aw |= (unsigned)a0 << (8 * j);
            if (a0) { s[0] += q0; s[1] += q1; s[2] += q2; s[3]++; }
            s[4] += q0; s[5] += q1; s[6] += q2;
        }
        // block-reduce 7 counters
#pragma unroll
        for (int k = 0; k < 7; k++) {
            int r = __reduce_add_sync(0xFFFFFFFFu, s[k]);
            if (lane == 0) sred[wid][k] = r;
        }
        __syncthreads();
        if (wid < 7) {
            int r = __reduce_add_sync(0xFFFFFFFFu, sred[lane][wid]);
            if (lane == 0) {
                if (wid < 4) atomicAdd(&g_acc[0][bb][wid], r);
                else         atomicAdd(&g_tot[bb][wid - 4], r);
            }
        }
        // publish boundary rows of alpha0
        if (lr == 0 || lr == 7)
            __stcg((unsigned*)g_alpha[0] + idx4, aw);
    }
    gbar(phase);

    // ---------- phase 3: 5 ICM iterations ----------
    for (int it = 0; it < NITER; ++it) {
        // means (threads 0..5, one division each)
        if (tid < 3) {
            int F  = __ldcg(&g_acc[it][bb][tid]);
            int Fc = __ldcg(&g_acc[it][bb][3]);
            sm_fm[tid] = __fdiv_rn((float)F, __fadd_rn((float)Fc, 1e-6f));
        } else if (tid < 6) {
            int F  = __ldcg(&g_acc[it][bb][tid - 3]);
            int Fc = __ldcg(&g_acc[it][bb][3]);
            int T  = __ldcg(&g_tot[bb][tid - 3]);
            sm_bm[tid - 3] = __fdiv_rn((float)(T - F),
                                       __fadd_rn((float)(HW - Fc), 1e-6f));
        }
        salpha[tid] = aw;
        __syncthreads();

        const unsigned* __restrict__ ga = (const unsigned*)g_alpha[it & 1];
        unsigned cen = aw;
        unsigned upw = (lr > 0) ? salpha[tid - 128]
                     : ((y > 0) ? __ldcg(ga + idx4 - 128) : cen);
        unsigned dnw = (lr < 7) ? salpha[tid + 128]
                     : ((y < Hn - 1) ? __ldcg(ga + idx4 + 128) : cen);
        unsigned lfb = (c > 0)   ? (salpha[tid - 1] >> 24) : (cen & 255u);
        unsigned rtb = (c < 127) ? (salpha[tid + 1] & 255u) : (cen >> 24);
        unsigned lfw = (cen << 8) | lfb;
        unsigned rtw = (cen >> 8) | (rtb << 24);
        unsigned nbw = __vadd4(__vadd4(upw, dnw), __vadd4(lfw, rtw));

        float fm0 = sm_fm[0], fm1 = sm_fm[1], fm2 = sm_fm[2];
        float bm0 = sm_bm[0], bm1 = sm_bm[1], bm2 = sm_bm[2];

        int av[4], s0 = 0, s1 = 0, s2 = 0, sc = 0;
#pragma unroll
        for (int j = 0; j < 4; j++) {
            unsigned w = wv[j];
            int qi0 = (int)(w & 255u), qi1 = (int)((w >> 8) & 255u),
                qi2 = (int)((w >> 16) & 255u);
            float i0 = (float)qi0, i1 = (float)qi1, i2 = (float)qi2;
            float nb = __fmul_rn((float)((nbw >> (8 * j)) & 255u), 0.25f);

            float d0 = __fsub_rn(i0, fm0);
            float d1 = __fsub_rn(i1, fm1);
            float d2 = __fsub_rn(i2, fm2);
            float dfg = __fadd_rn(__fadd_rn(__fmul_rn(d0, d0), __fmul_rn(d1, d1)),
                                  __fmul_rn(d2, d2));
            float e0 = __fsub_rn(i0, bm0);
            float e1 = __fsub_rn(i1, bm1);
            float e2 = __fsub_rn(i2, bm2);
            float dbg = __fadd_rn(__fadd_rn(__fmul_rn(e0, e0), __fmul_rn(e1, e1)),
                                  __fmul_rn(e2, e2));
            float pw = __fmul_rn(50.0f, __fsub_rn(__fmul_rn(2.0f, nb), 1.0f));
            float score = __fadd_rn(__fsub_rn(dbg, dfg), pw);

            int na = (score > 0.0f) ? 1 : 0;
            int a  = (w & 0x01000000u) ? (int)((w >> 25) & 1u) : na;
            av[j] = a;
            if (a) { s0 += qi0; s1 += qi1; s2 += qi2; sc++; }
        }
        aw = (unsigned)av[0] | ((unsigned)av[1] << 8)
           | ((unsigned)av[2] << 16) | ((unsigned)av[3] << 24);

        if (it == NITER - 1) {
            ((float4*)out)[idx4] = make_float4((float)av[0], (float)av[1],
                                               (float)av[2], (float)av[3]);
        } else {
            // publish boundary rows for next iteration
            if (lr == 0 || lr == 7)
                __stcg((unsigned*)g_alpha[(it + 1) & 1] + idx4, aw);
            // block-reduce next-iteration fg stats
            int s[4] = {s0, s1, s2, sc};
#pragma unroll
            for (int k = 0; k < 4; k++) {
                int r = __reduce_add_sync(0xFFFFFFFFu, s[k]);
                if (lane == 0) sred[wid][k] = r;
            }
            __syncthreads();
            if (wid < 4) {
                int r = __reduce_add_sync(0xFFFFFFFFu, sred[lane][wid]);
                if (lane == 0) atomicAdd(&g_acc[it + 1][bb][wid], r);
            }
            gbar(phase);
        }
    }
}

// ============================================================
extern "C" void kernel_launch(void* const* d_in, const int* in_sizes, int n_in,
                              void* d_out, int out_size) {
    const float* feat = (const float*)d_in[0];
    const int*   mask = (const int*)d_in[1];
    float*       out  = (float*)d_out;

    k_init<<<1, 64>>>();
    k_main<<<NB, NT>>>(feat, mask, out);
}